// round 1
// baseline (speedup 1.0000x reference)
#include <cuda_runtime.h>
#include <cuda_bf16.h>

// Problem constants
#define BB 8
#define CC 256
#define HH 128
#define WW 128
#define ND 64
#define KE 9     // K*K

// Scratch (allocation-free rule: __device__ globals)
__device__ float g_style[BB * CC];
__device__ float g_wmod[BB * CC * CC * KE];   // layout [b][i][o][9]  (~18 MB)

// ---------------------------------------------------------------------------
// Kernel 0: style[b][c] = sum_d nf[b][d] * mod_w[c][d] + mod_b[c]
// ---------------------------------------------------------------------------
__global__ void style_kernel(const float* __restrict__ nf,
                             const float* __restrict__ mw,
                             const float* __restrict__ mb) {
    int b = blockIdx.x;
    int c = threadIdx.x;
    const float* nfb = nf + b * ND;
    const float* mwc = mw + c * ND;
    float s = 0.f;
#pragma unroll
    for (int d = 0; d < ND; ++d) s += nfb[d] * mwc[d];
    g_style[b * CC + c] = s + mb[c];
}

// ---------------------------------------------------------------------------
// Kernel 1: per (b,o): v = scale*weight[o][i][k]*style[b][i];
//           demod = rsqrt(sum v^2 + 1e-8); store v*demod transposed [b][i][o][k]
// ---------------------------------------------------------------------------
__global__ void modw_kernel(const float* __restrict__ weight) {
    int o = blockIdx.x;
    int b = blockIdx.y;
    int i = threadIdx.x;                       // input channel
    const float scale = 1.0f / 48.0f;          // 1/sqrt(256*9)

    float s = g_style[b * CC + i] * scale;
    const float* wp = weight + (o * CC + i) * KE;
    float v[KE];
    float sq = 0.f;
#pragma unroll
    for (int k = 0; k < KE; ++k) {
        v[k] = wp[k] * s;
        sq += v[k] * v[k];
    }

    // block reduction over 256 threads
    __shared__ float red[8];
#pragma unroll
    for (int off = 16; off; off >>= 1) sq += __shfl_xor_sync(0xffffffffu, sq, off);
    if ((threadIdx.x & 31) == 0) red[threadIdx.x >> 5] = sq;
    __syncthreads();
    if (threadIdx.x < 8) {
        float t = red[threadIdx.x];
#pragma unroll
        for (int off = 4; off; off >>= 1) t += __shfl_xor_sync(0xffu, t, off);
        if (threadIdx.x == 0) red[0] = t;
    }
    __syncthreads();

    float demod = rsqrtf(red[0] + 1e-8f);
    float* dst = g_wmod + ((size_t)(b * CC + i) * CC + o) * KE;
#pragma unroll
    for (int k = 0; k < KE; ++k) dst[k] = v[k] * demod;
}

// ---------------------------------------------------------------------------
// Kernel 2: direct 3x3 conv, padding 1.
// Block = 64 output channels x 1 output row (128 px), 256 threads.
// Thread = 4 oc x 8 pixels (pixel stride 16 -> conflict-free LDS, coalesced STG).
// Per input channel: smem stage of fea halo (3x130) + weights (64x9),
// double-buffered with register prefetch; 1 barrier per channel.
// ---------------------------------------------------------------------------
__global__ __launch_bounds__(256, 3)
void conv_kernel(const float* __restrict__ fea, float* __restrict__ out) {
    const int r   = blockIdx.x;          // output row 0..127
    const int o0  = blockIdx.y * 64;     // oc tile base
    const int b   = blockIdx.z;
    const int tid = threadIdx.x;
    const int pxg = tid & 15;            // pixel group 0..15
    const int ocg = tid >> 4;            // oc group    0..15 (4 oc each)

    __shared__ float s_fea[2][390];      // 3 rows x 130 padded cols
    __shared__ float s_w[2][576];        // 64 oc x 9

    // Precompute the two fea gather offsets this thread uses every iteration.
    int off0, off1;
    {
        int idx = tid;
        int ry = idx / 130, cx = idx - ry * 130;
        int gr = r + ry - 1, gc = cx - 1;
        off0 = (gr >= 0 && gr < HH && gc >= 0 && gc < WW) ? gr * WW + gc : -1;

        idx = tid + 256;
        ry = idx / 130; cx = idx - ry * 130;
        gr = r + ry - 1; gc = cx - 1;
        off1 = (idx < 390 && gr >= 0 && gr < HH && gc >= 0 && gc < WW) ? gr * WW + gc : -1;
    }

    const float* fbase = fea + (size_t)(b * CC) * (HH * WW);
    const float* wbase = g_wmod + (size_t)b * CC * CC * KE + (size_t)o0 * KE;
    const int FSTRIDE = HH * WW;   // per input channel in fea
    const int WSTRIDE = CC * KE;   // per input channel in g_wmod (2304)

    // Prologue: stage channel 0
    {
        float f0 = (off0 >= 0) ? __ldg(fbase + off0) : 0.f;
        float f1 = (tid < 134 && off1 >= 0) ? __ldg(fbase + off1) : 0.f;
        float w0 = wbase[tid];
        float w1 = wbase[tid + 256];
        float w2 = (tid < 64) ? wbase[tid + 512] : 0.f;
        s_fea[0][tid] = f0;
        if (tid < 134) s_fea[0][tid + 256] = f1;
        s_w[0][tid] = w0;
        s_w[0][tid + 256] = w1;
        if (tid < 64) s_w[0][tid + 512] = w2;
    }
    __syncthreads();

    float acc[4][8];
#pragma unroll
    for (int o = 0; o < 4; ++o)
#pragma unroll
        for (int p = 0; p < 8; ++p) acc[o][p] = 0.f;

    for (int i = 0; i < CC; ++i) {
        const int buf = i & 1;

        // Prefetch next channel into registers (latency hidden by compute).
        float pf_f0 = 0.f, pf_f1 = 0.f, pf_w0 = 0.f, pf_w1 = 0.f, pf_w2 = 0.f;
        if (i < CC - 1) {
            const float* fch = fbase + (size_t)(i + 1) * FSTRIDE;
            if (off0 >= 0) pf_f0 = __ldg(fch + off0);
            if (tid < 134 && off1 >= 0) pf_f1 = __ldg(fch + off1);
            const float* wch = wbase + (size_t)(i + 1) * WSTRIDE;
            pf_w0 = wch[tid];
            pf_w1 = wch[tid + 256];
            if (tid < 64) pf_w2 = wch[tid + 512];
        }

        // Compute on current buffer.
        const float* fs = s_fea[buf];
        const float* ws = s_w[buf] + ocg * 4 * KE;
#pragma unroll
        for (int ky = 0; ky < 3; ++ky) {
            float wr[4][3];
#pragma unroll
            for (int o = 0; o < 4; ++o)
#pragma unroll
                for (int kx = 0; kx < 3; ++kx)
                    wr[o][kx] = ws[o * KE + ky * 3 + kx];
            const float* frow = fs + ky * 130 + pxg;
#pragma unroll
            for (int p = 0; p < 8; ++p) {
                float f0 = frow[16 * p];
                float f1 = frow[16 * p + 1];
                float f2 = frow[16 * p + 2];
#pragma unroll
                for (int o = 0; o < 4; ++o)
                    acc[o][p] += wr[o][0] * f0 + wr[o][1] * f1 + wr[o][2] * f2;
            }
        }

        // Commit prefetch into the other buffer.
        if (i < CC - 1) {
            const int nb = buf ^ 1;
            s_fea[nb][tid] = pf_f0;
            if (tid < 134) s_fea[nb][tid + 256] = pf_f1;
            s_w[nb][tid] = pf_w0;
            s_w[nb][tid + 256] = pf_w1;
            if (tid < 64) s_w[nb][tid + 512] = pf_w2;
        }
        __syncthreads();
    }

    // Epilogue: coalesced stores (16 consecutive lanes per pixel group).
    float* obase = out + ((size_t)(b * CC + o0 + ocg * 4) * HH + r) * WW + pxg;
#pragma unroll
    for (int o = 0; o < 4; ++o) {
        float* op = obase + (size_t)o * HH * WW;
#pragma unroll
        for (int p = 0; p < 8; ++p)
            op[16 * p] = acc[o][p];
    }
}

// ---------------------------------------------------------------------------
extern "C" void kernel_launch(void* const* d_in, const int* in_sizes, int n_in,
                              void* d_out, int out_size) {
    const float* fea    = (const float*)d_in[0];   // (8,256,128,128)
    const float* nf     = (const float*)d_in[1];   // (8,64,1,1)
    const float* mw     = (const float*)d_in[2];   // (256,64,1,1)
    const float* mb     = (const float*)d_in[3];   // (256,)
    const float* weight = (const float*)d_in[4];   // (1,256,256,3,3)
    float* out = (float*)d_out;                    // (8,256,128,128)

    style_kernel<<<BB, CC>>>(nf, mw, mb);
    modw_kernel<<<dim3(CC, BB), CC>>>(weight);
    conv_kernel<<<dim3(HH, CC / 64, BB), 256>>>(fea, out);
}

// round 2
// speedup vs baseline: 1.5474x; 1.5474x over previous
#include <cuda_runtime.h>
#include <cuda_bf16.h>

// Problem constants
#define BB 8
#define CC 256
#define HH 128
#define WW 128
#define ND 64
#define KE 9     // K*K

typedef unsigned long long u64;

// Scratch (allocation-free rule: __device__ globals)
__device__ float g_style[BB * CC];
__device__ float g_wmod[BB * CC * CC * KE];   // layout [b][i][o][9]  (~18 MB)

// ---- packed f32x2 helpers (Blackwell FFMA2) --------------------------------
__device__ __forceinline__ void ffma2(u64& d, u64 a, u64 b) {
    asm("fma.rn.f32x2 %0, %1, %2, %0;" : "+l"(d) : "l"(a), "l"(b));
}
__device__ __forceinline__ u64 pk(float lo, float hi) {
    u64 r; asm("mov.b64 %0, {%1, %2};" : "=l"(r) : "f"(lo), "f"(hi)); return r;
}

// ---------------------------------------------------------------------------
// Kernel 0: style[b][c] = sum_d nf[b][d] * mod_w[c][d] + mod_b[c]
// ---------------------------------------------------------------------------
__global__ void style_kernel(const float* __restrict__ nf,
                             const float* __restrict__ mw,
                             const float* __restrict__ mb) {
    int b = blockIdx.x;
    int c = threadIdx.x;
    const float* nfb = nf + b * ND;
    const float* mwc = mw + c * ND;
    float s = 0.f;
#pragma unroll
    for (int d = 0; d < ND; ++d) s += nfb[d] * mwc[d];
    g_style[b * CC + c] = s + mb[c];
}

// ---------------------------------------------------------------------------
// Kernel 1: per (b,o): v = scale*weight[o][i][k]*style[b][i];
//           demod = rsqrt(sum v^2 + 1e-8); store v*demod transposed [b][i][o][9]
// ---------------------------------------------------------------------------
__global__ void modw_kernel(const float* __restrict__ weight) {
    int o = blockIdx.x;
    int b = blockIdx.y;
    int i = threadIdx.x;                       // input channel
    const float scale = 1.0f / 48.0f;          // 1/sqrt(256*9)

    float s = g_style[b * CC + i] * scale;
    const float* wp = weight + (o * CC + i) * KE;
    float v[KE];
    float sq = 0.f;
#pragma unroll
    for (int k = 0; k < KE; ++k) {
        v[k] = wp[k] * s;
        sq += v[k] * v[k];
    }

    __shared__ float red[8];
#pragma unroll
    for (int off = 16; off; off >>= 1) sq += __shfl_xor_sync(0xffffffffu, sq, off);
    if ((threadIdx.x & 31) == 0) red[threadIdx.x >> 5] = sq;
    __syncthreads();
    if (threadIdx.x < 8) {
        float t = red[threadIdx.x];
#pragma unroll
        for (int off = 4; off; off >>= 1) t += __shfl_xor_sync(0xffu, t, off);
        if (threadIdx.x == 0) red[0] = t;
    }
    __syncthreads();

    float demod = rsqrtf(red[0] + 1e-8f);
    float* dst = g_wmod + ((size_t)(b * CC + i) * CC + o) * KE;
#pragma unroll
    for (int k = 0; k < KE; ++k) dst[k] = v[k] * demod;
}

// ---------------------------------------------------------------------------
// Kernel 2: direct 3x3 conv, padding 1, packed-f32x2 math.
// Block = 64 output channels x 1 output row (128 px), 256 threads.
// Thread: ocg = tid>>4 -> 4 output channels; pxq = tid&15 -> two pixel quads
//   [4*pxq .. 4*pxq+3] and [64+4*pxq .. 64+4*pxq+3].
// Accumulators: acc[4 oc][4 f32x2 pairs] (pairs of adjacent pixels).
// Per input channel: smem stage of fea halo (3x130, padded stride 132) and
// weights duplicated as float2{w,w}; double-buffered, 1 barrier/channel.
// ---------------------------------------------------------------------------
__global__ __launch_bounds__(256, 2)
void conv_kernel(const float* __restrict__ fea, float* __restrict__ out) {
    const int r   = blockIdx.x;          // output row 0..127
    const int o0  = blockIdx.y * 64;     // oc tile base
    const int b   = blockIdx.z;
    const int tid = threadIdx.x;
    const int pxq = tid & 15;            // pixel-quad group 0..15
    const int ocg = tid >> 4;            // oc group 0..15 (4 oc each)

    __shared__ __align__(16) float  s_fea[2][3 * 132];   // padded stride 132
    __shared__ __align__(16) float2 s_wd[2][KE * 64];    // [k][o] = {w,w}

    // --- precompute staging offsets (constant across channels) -------------
    int off0, off1, t0, t1;
    {
        int ry = tid / 130, cx = tid - ry * 130;
        int gr = r + ry - 1, gc = cx - 1;
        off0 = (gr >= 0 && gr < HH && gc >= 0 && gc < WW) ? gr * WW + gc : -1;
        t0 = ry * 132 + cx;

        int idx = tid + 256;
        ry = idx / 130; cx = idx - ry * 130;
        gr = r + ry - 1; gc = cx - 1;
        off1 = (idx < 390 && gr >= 0 && gr < HH && gc >= 0 && gc < WW) ? gr * WW + gc : -1;
        t1 = ry * 132 + cx;
    }
    // weight staging: idx -> (o = idx/9, k = idx%9) -> smem slot k*64+o
    int wt0, wt1, wt2;
    {
        int o = tid / 9,          k = tid - 9 * o;           wt0 = k * 64 + o;
        o = (tid + 256) / 9;      k = (tid + 256) - 9 * o;   wt1 = k * 64 + o;
        o = (tid + 512) / 9;      k = (tid + 512) - 9 * o;   wt2 = k * 64 + o;
    }

    // zero the padding columns (130,131) so no NaN junk is ever loaded
    if (tid < 12) {
        int row = tid >> 2, bf = (tid >> 1) & 1, col = 130 + (tid & 1);
        s_fea[bf][row * 132 + col] = 0.f;
        s_fea[bf ^ 1][row * 132 + col] = 0.f;
    }

    const float* fbase = fea + (size_t)(b * CC) * (HH * WW);
    const float* wbase = g_wmod + (size_t)b * CC * CC * KE + (size_t)o0 * KE;
    const int FSTRIDE = HH * WW;
    const int WSTRIDE = CC * KE;   // 2304

    // --- prologue: stage channel 0 ------------------------------------------
    {
        float f0 = (off0 >= 0) ? __ldg(fbase + off0) : 0.f;
        float f1 = (tid < 134 && off1 >= 0) ? __ldg(fbase + off1) : 0.f;
        float w0 = wbase[tid];
        float w1 = wbase[tid + 256];
        float w2 = (tid < 64) ? wbase[tid + 512] : 0.f;
        s_fea[0][t0] = f0;
        if (tid < 134) s_fea[0][t1] = f1;
        s_wd[0][wt0] = make_float2(w0, w0);
        s_wd[0][wt1] = make_float2(w1, w1);
        if (tid < 64) s_wd[0][wt2] = make_float2(w2, w2);
    }
    __syncthreads();

    u64 acc[4][4];
#pragma unroll
    for (int o = 0; o < 4; ++o)
#pragma unroll
        for (int p = 0; p < 4; ++p) acc[o][p] = 0ULL;

    for (int i = 0; i < CC; ++i) {
        const int buf = i & 1;

        // prefetch next channel into registers
        float pf_f0 = 0.f, pf_f1 = 0.f, pf_w0 = 0.f, pf_w1 = 0.f, pf_w2 = 0.f;
        if (i < CC - 1) {
            const float* fch = fbase + (size_t)(i + 1) * FSTRIDE;
            if (off0 >= 0) pf_f0 = __ldg(fch + off0);
            if (tid < 134 && off1 >= 0) pf_f1 = __ldg(fch + off1);
            const float* wch = wbase + (size_t)(i + 1) * WSTRIDE;
            pf_w0 = wch[tid];
            pf_w1 = wch[tid + 256];
            if (tid < 64) pf_w2 = wch[tid + 512];
        }

        // compute on current buffers
        const float*  fs = s_fea[buf];
        const float2* ws = s_wd[buf] + ocg * 4;
#pragma unroll
        for (int ky = 0; ky < 3; ++ky) {
            // 12 broadcast weight pairs for this ky (LDS.64 each)
            u64 w[4][3];
#pragma unroll
            for (int kx = 0; kx < 3; ++kx) {
                const float2* wp = ws + (ky * 3 + kx) * 64;
#pragma unroll
                for (int o = 0; o < 4; ++o)
                    w[o][kx] = *(const u64*)(wp + o);
            }
#pragma unroll
            for (int g = 0; g < 2; ++g) {
                const float* fr = fs + ky * 132 + 4 * pxq + 64 * g;
                float4 Fa = *(const float4*)(fr);       // f0..f3 (16B aligned)
                float4 Fb = *(const float4*)(fr + 4);   // f4..f7
                u64 P0 = pk(Fa.x, Fa.y);
                u64 P1 = pk(Fa.y, Fa.z);
                u64 P2 = pk(Fa.z, Fa.w);
                u64 P3 = pk(Fa.w, Fb.x);
                u64 P4 = pk(Fb.x, Fb.y);
#pragma unroll
                for (int o = 0; o < 4; ++o) {
                    ffma2(acc[o][2 * g],     w[o][0], P0);
                    ffma2(acc[o][2 * g],     w[o][1], P1);
                    ffma2(acc[o][2 * g],     w[o][2], P2);
                    ffma2(acc[o][2 * g + 1], w[o][0], P2);
                    ffma2(acc[o][2 * g + 1], w[o][1], P3);
                    ffma2(acc[o][2 * g + 1], w[o][2], P4);
                }
            }
        }

        // commit prefetch into the other buffer
        if (i < CC - 1) {
            const int nb = buf ^ 1;
            s_fea[nb][t0] = pf_f0;
            if (tid < 134) s_fea[nb][t1] = pf_f1;
            s_wd[nb][wt0] = make_float2(pf_w0, pf_w0);
            s_wd[nb][wt1] = make_float2(pf_w1, pf_w1);
            if (tid < 64) s_wd[nb][wt2] = make_float2(pf_w2, pf_w2);
        }
        __syncthreads();
    }

    // --- epilogue: stores (lanes 0-15 cover 256B contiguous per oc) --------
    float* obase = out + ((size_t)(b * CC + o0 + ocg * 4) * HH + r) * WW + 4 * pxq;
#pragma unroll
    for (int o = 0; o < 4; ++o) {
        float* op = obase + (size_t)o * HH * WW;
        u64* q0 = (u64*)op;
        q0[0] = acc[o][0];
        q0[1] = acc[o][1];
        u64* q1 = (u64*)(op + 64);
        q1[0] = acc[o][2];
        q1[1] = acc[o][3];
    }
}

// ---------------------------------------------------------------------------
extern "C" void kernel_launch(void* const* d_in, const int* in_sizes, int n_in,
                              void* d_out, int out_size) {
    const float* fea    = (const float*)d_in[0];   // (8,256,128,128)
    const float* nf     = (const float*)d_in[1];   // (8,64,1,1)
    const float* mw     = (const float*)d_in[2];   // (256,64,1,1)
    const float* mb     = (const float*)d_in[3];   // (256,)
    const float* weight = (const float*)d_in[4];   // (1,256,256,3,3)
    float* out = (float*)d_out;                    // (8,256,128,128)

    style_kernel<<<BB, CC>>>(nf, mw, mb);
    modw_kernel<<<dim3(CC, BB), CC>>>(weight);
    conv_kernel<<<dim3(HH, CC / 64, BB), 256>>>(fea, out);
}

// round 4
// speedup vs baseline: 4.7950x; 3.0988x over previous
#include <cuda_runtime.h>
#include <cuda_bf16.h>
#include <cstdint>

// Problem constants
#define BB 8
#define CC 256
#define HH 128
#define WW 128
#define ND 64

// ---------------------------------------------------------------------------
// Scratch (__device__ globals; no runtime allocation)
// ---------------------------------------------------------------------------
__device__ float g_style[BB * CC];
// Weights, modulated+demodulated, split bf16, layout [b][tap][oc][i]
__device__ __align__(256) __nv_bfloat16 g_Ahi[BB * 9 * CC * CC];
__device__ __align__(256) __nv_bfloat16 g_Alo[BB * 9 * CC * CC];
// fea transposed to [b][y][x][c], split bf16
__device__ __align__(256) __nv_bfloat16 g_Fhi[(size_t)BB * HH * WW * CC];
__device__ __align__(256) __nv_bfloat16 g_Flo[(size_t)BB * HH * WW * CC];

// ---------------------------------------------------------------------------
// PTX helpers (all sm_80-era: compile on compute_103)
// ---------------------------------------------------------------------------
__device__ __forceinline__ uint32_t smem_u32(const void* p) {
    uint32_t a;
    asm("{ .reg .u64 t; cvta.to.shared.u64 t, %1; cvt.u32.u64 %0, t; }" : "=r"(a) : "l"(p));
    return a;
}
__device__ __forceinline__ void cpa16(uint32_t dst, const void* src, uint32_t bytes) {
    asm volatile("cp.async.cg.shared.global [%0], [%1], 16, %2;"
                 :: "r"(dst), "l"(src), "r"(bytes) : "memory");
}
__device__ __forceinline__ void cpa_commit() {
    asm volatile("cp.async.commit_group;" ::: "memory");
}
__device__ __forceinline__ void cpa_wait2() {
    asm volatile("cp.async.wait_group 2;" ::: "memory");
}
__device__ __forceinline__ uint32_t swz(uint32_t off) { return off ^ ((off >> 3) & 0x70); }

__device__ __forceinline__ void ldsm_x4(uint32_t& r0, uint32_t& r1, uint32_t& r2, uint32_t& r3,
                                        uint32_t addr) {
    asm volatile("ldmatrix.sync.aligned.m8n8.x4.shared.b16 {%0,%1,%2,%3}, [%4];"
                 : "=r"(r0), "=r"(r1), "=r"(r2), "=r"(r3) : "r"(addr));
}
__device__ __forceinline__ void ldsm_x2(uint32_t& r0, uint32_t& r1, uint32_t addr) {
    asm volatile("ldmatrix.sync.aligned.m8n8.x2.shared.b16 {%0,%1}, [%2];"
                 : "=r"(r0), "=r"(r1) : "r"(addr));
}
__device__ __forceinline__ void mma_bf16(float* d, const uint32_t* a, const uint32_t* b) {
    asm volatile(
        "mma.sync.aligned.m16n8k16.row.col.f32.bf16.bf16.f32 "
        "{%0,%1,%2,%3}, {%4,%5,%6,%7}, {%8,%9}, {%0,%1,%2,%3};"
        : "+f"(d[0]), "+f"(d[1]), "+f"(d[2]), "+f"(d[3])
        : "r"(a[0]), "r"(a[1]), "r"(a[2]), "r"(a[3]), "r"(b[0]), "r"(b[1]));
}

// ---------------------------------------------------------------------------
// Kernel 0: style
// ---------------------------------------------------------------------------
__global__ void style_kernel(const float* __restrict__ nf,
                             const float* __restrict__ mw,
                             const float* __restrict__ mb) {
    int b = blockIdx.x, c = threadIdx.x;
    const float* nfb = nf + b * ND;
    const float* mwc = mw + c * ND;
    float s = 0.f;
#pragma unroll
    for (int d = 0; d < ND; ++d) s += nfb[d] * mwc[d];
    g_style[b * CC + c] = s + mb[c];
}

// ---------------------------------------------------------------------------
// Kernel 1: modulate + demod weights, split bf16, layout [b][tap][oc][i]
// ---------------------------------------------------------------------------
__global__ void modw_kernel(const float* __restrict__ weight) {
    int o = blockIdx.x, b = blockIdx.y, i = threadIdx.x;
    const float scale = 1.0f / 48.0f;
    float s = g_style[b * CC + i] * scale;
    const float* wp = weight + (o * CC + i) * 9;
    float v[9];
    float sq = 0.f;
#pragma unroll
    for (int k = 0; k < 9; ++k) { v[k] = wp[k] * s; sq += v[k] * v[k]; }

    __shared__ float red[8];
#pragma unroll
    for (int off = 16; off; off >>= 1) sq += __shfl_xor_sync(0xffffffffu, sq, off);
    if ((threadIdx.x & 31) == 0) red[threadIdx.x >> 5] = sq;
    __syncthreads();
    if (threadIdx.x < 8) {
        float t = red[threadIdx.x];
#pragma unroll
        for (int off = 4; off; off >>= 1) t += __shfl_xor_sync(0xffu, t, off);
        if (threadIdx.x == 0) red[0] = t;
    }
    __syncthreads();
    float demod = rsqrtf(red[0] + 1e-8f);
#pragma unroll
    for (int k = 0; k < 9; ++k) {
        float val = v[k] * demod;
        __nv_bfloat16 hi = __float2bfloat16(val);
        float lof = val - __bfloat162float(hi);
        size_t idx = ((size_t)((b * 9 + k) * CC) + o) * CC + i;
        g_Ahi[idx] = hi;
        g_Alo[idx] = __float2bfloat16(lof);
    }
}

// ---------------------------------------------------------------------------
// Kernel 2: fea NCHW -> [b][y][x][c] with bf16 hi/lo split
// ---------------------------------------------------------------------------
__global__ __launch_bounds__(256)
void tsplit_kernel(const float* __restrict__ fea) {
    int y = blockIdx.x, b = blockIdx.y;
    __shared__ float t[64][129];
    for (int cc = 0; cc < 4; ++cc) {
#pragma unroll
        for (int k = 0; k < 32; ++k) {
            int idx = threadIdx.x + k * 256;
            int cs = idx >> 7, x = idx & 127;
            t[cs][x] = fea[(((size_t)(b * CC + cc * 64 + cs)) * HH + y) * WW + x];
        }
        __syncthreads();
#pragma unroll
        for (int k = 0; k < 32; ++k) {
            int idx = threadIdx.x + k * 256;
            int c2 = idx & 63, x = idx >> 6;
            float v = t[c2][x];
            __nv_bfloat16 hi = __float2bfloat16(v);
            size_t o = ((size_t)((b * HH + y) * WW + x)) * CC + cc * 64 + c2;
            g_Fhi[o] = hi;
            g_Flo[o] = __float2bfloat16(v - __bfloat162float(hi));
        }
        __syncthreads();
    }
}

// ---------------------------------------------------------------------------
// Kernel 3: implicit-GEMM conv via mma.sync (split-bf16, 3 terms)
// grid (y=128, mtile=2, b=8); 256 threads = 8 warps (2M x 4N), warp tile 64x32
// K-loop: 36 steps = 9 taps x 4 chunks of 64 ch; 3-stage cp.async ring.
// Stage layout (64KB): Ah@0 Al@16K Bh@32K Bl@48K; each 128 rows x 128B, SW128.
// ---------------------------------------------------------------------------
#define NSTAGE 3
#define STAGE_BYTES 65536
#define SMEM_TOTAL (NSTAGE * STAGE_BYTES)

__global__ __launch_bounds__(256, 1)
void gemm_kernel(float* __restrict__ out) {
    extern __shared__ char smem[];
    const uint32_t sb = smem_u32(smem);
    const int tid  = threadIdx.x;
    const int lane = tid & 31;
    const int wid  = tid >> 5;
    const int warpM = wid >> 2;   // 0..1
    const int warpN = wid & 3;    // 0..3
    const int y = blockIdx.x, mt = blockIdx.y, b = blockIdx.z;

    // ---- producer constants ----
    const int prow = tid >> 1;      // 0..127 (oc-row for A, pixel for B)
    const int part = tid & 1;       // 64B half of the 128B row
    const uint32_t rowoff = (uint32_t)prow * 128u + (uint32_t)part * 64u;
    const size_t abase = ((size_t)(b * 9) * CC + (size_t)mt * 128 + prow) * CC;

    // issue cp.async for one stage
    auto issue = [&](int step, int buf) {
        const int tap = step >> 2, ck = step & 3;
        const uint32_t stg = sb + (uint32_t)buf * STAGE_BYTES;
        const size_t aoff = abase + (size_t)tap * CC * CC + ck * 64 + part * 32;
        const __nv_bfloat16* srcAh = g_Ahi + aoff;
        const __nv_bfloat16* srcAl = g_Alo + aoff;
        const int yy = y + tap / 3 - 1;
        const int xx = prow + tap % 3 - 1;
        const bool bv = (yy >= 0 && yy < HH && xx >= 0 && xx < WW);
        const size_t boff = ((size_t)((b * HH + (bv ? yy : 0)) * WW + (bv ? xx : 0))) * CC
                            + ck * 64 + part * 32;
        const __nv_bfloat16* srcBh = g_Fhi + boff;
        const __nv_bfloat16* srcBl = g_Flo + boff;
        const uint32_t bsz = bv ? 16u : 0u;
#pragma unroll
        for (int j = 0; j < 4; ++j) {
            const uint32_t d = swz(rowoff + j * 16u);
            cpa16(stg + d,          srcAh + j * 8, 16u);
            cpa16(stg + 16384u + d, srcAl + j * 8, 16u);
            cpa16(stg + 32768u + d, srcBh + j * 8, bsz);
            cpa16(stg + 49152u + d, srcBl + j * 8, bsz);
        }
    };

    // ---- consumer address bases (offsets within a stage, pre-swizzle) ----
    // A (ldmatrix.x4): row = warpM*64 + m*16 + (lane&15); colB = (lane>>4)*16 + kk*32
    const uint32_t aRowB = ((uint32_t)warpM * 64u + (lane & 15)) * 128u + ((lane >> 4) * 16u);
    // B (ldmatrix.x2): row = warpN*32 + n*8 + (lane&7); colB = ((lane>>3)&1)*16 + kk*32
    const uint32_t bRowB = ((uint32_t)warpN * 32u + (lane & 7)) * 128u + (((lane >> 3) & 1) * 16u);

    float acc[4][4][4];
#pragma unroll
    for (int m = 0; m < 4; ++m)
#pragma unroll
        for (int n = 0; n < 4; ++n)
#pragma unroll
            for (int i = 0; i < 4; ++i) acc[m][n][i] = 0.f;

    // prologue: stages 0,1
    issue(0, 0); cpa_commit();
    issue(1, 1); cpa_commit();

#pragma unroll 1
    for (int s = 0; s < 36; ++s) {
        if (s + 2 < 36) issue(s + 2, (s + 2) % NSTAGE);
        cpa_commit();                 // uniform group count (empty at tail)
        cpa_wait2();                  // stage s complete (this thread)
        __syncthreads();              // all threads' copies complete

        const uint32_t stg = sb + (uint32_t)(s % NSTAGE) * STAGE_BYTES;
        const uint32_t aBase = stg + 0u;
        const uint32_t bBase = stg + 32768u;

#pragma unroll
        for (int kk = 0; kk < 4; ++kk) {
            uint32_t Ah[4][4], Al[4][4], Bh[4][2], Bl[4][2];
#pragma unroll
            for (int m = 0; m < 4; ++m) {
                const uint32_t off = swz(aRowB + (uint32_t)m * 2048u + (uint32_t)kk * 32u);
                ldsm_x4(Ah[m][0], Ah[m][1], Ah[m][2], Ah[m][3], aBase + off);
                ldsm_x4(Al[m][0], Al[m][1], Al[m][2], Al[m][3], aBase + 16384u + off);
            }
#pragma unroll
            for (int n = 0; n < 4; ++n) {
                const uint32_t off = swz(bRowB + (uint32_t)n * 1024u + (uint32_t)kk * 32u);
                ldsm_x2(Bh[n][0], Bh[n][1], bBase + off);
                ldsm_x2(Bl[n][0], Bl[n][1], bBase + 16384u + off);
            }
#pragma unroll
            for (int m = 0; m < 4; ++m)
#pragma unroll
                for (int n = 0; n < 4; ++n) {
                    mma_bf16(acc[m][n], Ah[m], Bh[n]);
                    mma_bf16(acc[m][n], Ah[m], Bl[n]);
                    mma_bf16(acc[m][n], Al[m], Bh[n]);
                }
        }
        __syncthreads();              // protect buffer before it is re-filled
    }

    // ---- epilogue: direct stores (each 4-lane group = one 32B sector) ----
    const int r0 = mt * 128 + warpM * 64 + (lane >> 2);
    const int xc = warpN * 32 + (lane & 3) * 2;
#pragma unroll
    for (int m = 0; m < 4; ++m) {
#pragma unroll
        for (int n = 0; n < 4; ++n) {
            float* p0 = out + (((size_t)(b * CC + r0 + m * 16) * HH + y) * WW) + xc + n * 8;
            float* p1 = p0 + (size_t)8 * HH * WW;
            *(float2*)p0 = make_float2(acc[m][n][0], acc[m][n][1]);
            *(float2*)p1 = make_float2(acc[m][n][2], acc[m][n][3]);
        }
    }
}

// ---------------------------------------------------------------------------
extern "C" void kernel_launch(void* const* d_in, const int* in_sizes, int n_in,
                              void* d_out, int out_size) {
    const float* fea    = (const float*)d_in[0];
    const float* nf     = (const float*)d_in[1];
    const float* mw     = (const float*)d_in[2];
    const float* mb     = (const float*)d_in[3];
    const float* weight = (const float*)d_in[4];
    float* out = (float*)d_out;

    cudaFuncSetAttribute(gemm_kernel, cudaFuncAttributeMaxDynamicSharedMemorySize, SMEM_TOTAL);

    style_kernel<<<BB, CC>>>(nf, mw, mb);
    modw_kernel<<<dim3(CC, BB), CC>>>(weight);
    tsplit_kernel<<<dim3(HH, BB), 256>>>(fea);
    gemm_kernel<<<dim3(HH, 2, BB), 256, SMEM_TOTAL>>>(out);
}